// round 5
// baseline (speedup 1.0000x reference)
#include <cuda_runtime.h>
#include <cuda_pipeline.h>
#include <cstdint>

// CTC batch cost, forward (loss only). B=128, T=1024, C=256 (blank=255),
// Lmax=64, S=129.
//
//  - one warp (one CTA) per batch element; 5 states/thread (160 >= 129, masked)
//  - alpha recurrence in PROBABILITY domain: 3 FMA-class ops/state
//  - per-thread block-floating-point scales with neighbor-ratio halo rescale.
//    FRONTIER FIX (this round): inactive threads (local max == 0) adopt the
//    multiplier of the nearest active thread below (5-shfl scan), keeping all
//    beyond-frontier sigmas synchronized with the frontier sigma => rho stays
//    exactly 1 at every not-yet-crossed boundary, no overflow/underflow.
//    Scan only needed while the frontier exists (t < ~128): chunks >= 16 use a
//    scan-free renorm.
//  - chunked cp.async ring: 32 stages, 24 rows ahead, one wait+syncwarp/chunk.

#define T_DIM   1024
#define C_DIM   256
#define LMAX    64
#define PSTATES 5
#define NSTAGE  32
#define PFROWS  24
#define CHUNK   8
#define NCHUNK  (T_DIM / CHUNK)
#define SCANCH  16          // chunks using the frontier-safe scan renorm
#define EPSF    1e-7f
#define MFLOOR  1e-37f

__global__ __launch_bounds__(32, 1)
void ctc_loss_kernel(const int*   __restrict__ y_true,   // [B, LMAX]
                     const float* __restrict__ y_pred,   // [B, T, C]
                     const int*   __restrict__ in_len,   // [B, 1]
                     const int*   __restrict__ lab_len,  // [B, 1]
                     float*       __restrict__ out)      // [B, 1]
{
    __shared__ __align__(16) float stage[NSTAGE * C_DIM];
    __shared__ float fin_a [32 * PSTATES];
    __shared__ float fin_lc[32];

    const int b   = blockIdx.x;
    const int tid = threadIdx.x;
    const float* __restrict__ base = y_pred + (size_t)b * T_DIM * C_DIM;
    const int L    = lab_len[b];
    const int Tlen = in_len[b];
    const int Smax = 2 * L + 1;
    const int* __restrict__ yb = y_true + b * LMAX;

    // ---- per-state constants ----
    int   cls[PSTATES];
    float vm [PSTATES];   // 1 if state valid (s < Smax), else 0
    float evm[PSTATES];   // EPS * vm (eps folded into gather fma)
    float m1 [PSTATES];   // a[s-1] allowed (s >= 1)
    float m2 [PSTATES];   // skip: s odd, s>=3, label != prev label
    #pragma unroll
    for (int j = 0; j < PSTATES; j++) {
        int s   = tid * PSTATES + j;
        int odd = s & 1;
        int li  = (s - 1) >> 1;
        int c   = (odd && li >= 0 && li < LMAX) ? yb[li] : (C_DIM - 1);
        bool valid = (s < Smax);
        cls[j] = c;
        vm [j] = valid ? 1.0f : 0.0f;
        evm[j] = valid ? EPSF : 0.0f;
        m1 [j] = (s >= 1) ? 1.0f : 0.0f;
        bool skip = odd && (s >= 3) && (li < LMAX) && (yb[li] != yb[li - 1]);
        m2 [j] = skip ? 1.0f : 0.0f;
    }

    // ---- async copy of one emission row (1 KB); always commits one group ----
    auto issue = [&](int t) {
        if (t < T_DIM) {
            const float4* src = (const float4*)(base + (size_t)t * C_DIM);
            float4*       dst = (float4*)&stage[(t & (NSTAGE - 1)) * C_DIM];
            __pipeline_memcpy_async(&dst[tid],      &src[tid],      16);
            __pipeline_memcpy_async(&dst[tid + 32], &src[tid + 32], 16);
        }
        __pipeline_commit();
    };

    float a[PSTATES];
    float logacc = 0.0f;   // log sigma_i (per-thread scale)
    float rho    = 1.0f;   // sigma_{i-1} / sigma_i (halo rescale factor)

    // one recurrence step
    auto step = [&](int t) {
        const float* __restrict__ row = &stage[(t & (NSTAGE - 1)) * C_DIM];
        if (t < Tlen) {
            float h1 = __shfl_up_sync(0xffffffffu, a[PSTATES - 1], 1) * rho;
            float h2 = __shfl_up_sync(0xffffffffu, a[PSTATES - 2], 1) * rho;
            float na[PSTATES];
            #pragma unroll
            for (int j = 0; j < PSTATES; j++) {
                float a1 = (j == 0) ? h1 : a[j - 1];
                float a2 = (j == 0) ? h2 : ((j == 1) ? h1 : a[j - 2]);
                float p  = fmaf(row[cls[j]], vm[j], evm[j]);   // (y+eps) or 0
                float sm = fmaf(a1, m1[j], a[j]);
                sm       = fmaf(a2, m2[j], sm);
                na[j]    = sm * p;
            }
            #pragma unroll
            for (int j = 0; j < PSTATES; j++) a[j] = na[j];
        }
    };

    auto apply_scale = [&](float v) {
        float mprev = __shfl_up_sync(0xffffffffu, v, 1);   // lane0: own v
        float rinv  = __fdividef(1.0f, v);
        logacc += __logf(v);
        rho = rho * (mprev * rinv);
        #pragma unroll
        for (int j = 0; j < PSTATES; j++) a[j] *= rinv;
    };

    // frontier-safe renorm: inactive threads adopt nearest active-below's max
    auto renorm_scan = [&]() {
        float lm = fmaxf(fmaxf(fmaxf(a[0], a[1]), fmaxf(a[2], a[3])), a[4]);
        float v  = lm;
        #pragma unroll
        for (int d = 1; d < 32; d <<= 1) {
            float up = __shfl_up_sync(0xffffffffu, v, d);
            v = (v > 0.0f) ? v : up;     // first nonzero toward lane 0
        }
        v = fmaxf(v, MFLOOR);            // lane 0 is always active; pure guard
        apply_scale(v);
    };

    // post-frontier renorm: every valid reachable thread is active forever
    auto renorm_fast = [&]() {
        float lm = fmaxf(fmaxf(fmaxf(a[0], a[1]), fmaxf(a[2], a[3])), a[4]);
        apply_scale(fmaxf(lm, MFLOOR));  // floor only hits fully-invalid threads
    };

    // ---- prologue ----
    for (int k = 0; k < PFROWS; k++) issue(k);

    // ---- chunk 0: init at t=0, steps 1..7 ----
    __pipeline_wait_prior(PFROWS - CHUNK);
    __syncwarp();
    {
        const float* __restrict__ row = &stage[0];
        #pragma unroll
        for (int j = 0; j < PSTATES; j++) {
            int s   = tid * PSTATES + j;
            float p = fmaf(row[cls[j]], vm[j], evm[j]);
            a[j]    = (s < 2) ? p : 0.0f;
        }
    }
    #pragma unroll
    for (int t = 1; t < CHUNK; t++) step(t);
    renorm_scan();
    #pragma unroll
    for (int k = 0; k < CHUNK; k++) issue(PFROWS + k);

    // ---- chunks 1..15: frontier may still exist ----
    for (int c = 1; c < SCANCH; c++) {
        const int t0 = c * CHUNK;
        __pipeline_wait_prior(PFROWS - CHUNK);
        __syncwarp();
        #pragma unroll
        for (int i = 0; i < CHUNK; i++) step(t0 + i);
        renorm_scan();
        #pragma unroll
        for (int k = 0; k < CHUNK; k++) issue(t0 + PFROWS + k);
    }

    // ---- chunks 16..127: steady state ----
    for (int c = SCANCH; c < NCHUNK; c++) {
        const int t0 = c * CHUNK;
        __pipeline_wait_prior(PFROWS - CHUNK);
        __syncwarp();
        #pragma unroll
        for (int i = 0; i < CHUNK; i++) step(t0 + i);
        renorm_fast();
        #pragma unroll
        for (int k = 0; k < CHUNK; k++) issue(t0 + PFROWS + k);
    }

    // ---- finalize: ll = logaddexp over the two end states ----
    __syncwarp();
    #pragma unroll
    for (int j = 0; j < PSTATES; j++) fin_a[tid * PSTATES + j] = a[j];
    fin_lc[tid] = logacc;
    __syncwarp();
    if (tid == 0) {
        int  sa = 2 * L;
        int  sb = 2 * L - 1;                  // L >= 1 per setup
        float xa = __logf(fmaxf(fin_a[sa], 1e-37f)) + fin_lc[sa / PSTATES];
        float xb = __logf(fmaxf(fin_a[sb], 1e-37f)) + fin_lc[sb / PSTATES];
        float mxx = fmaxf(xa, xb);
        float mnn = fminf(xa, xb);
        float ll  = mxx + __logf(1.0f + __expf(mnn - mxx));
        out[b] = -ll;
    }
}

extern "C" void kernel_launch(void* const* d_in, const int* in_sizes, int n_in,
                              void* d_out, int out_size) {
    const int*   y_true  = (const int*)  d_in[0];   // [B,64] int32
    const float* y_pred  = (const float*)d_in[1];   // [B,1024,256] fp32
    const int*   in_len  = (const int*)  d_in[2];   // [B,1] int32
    const int*   lab_len = (const int*)  d_in[3];   // [B,1] int32
    float*       out     = (float*)      d_out;     // [B,1] fp32

    const int B = out_size;                          // 128
    ctc_loss_kernel<<<B, 32>>>(y_true, y_pred, in_len, lab_len, out);
}

// round 6
// speedup vs baseline: 1.0004x; 1.0004x over previous
#include <cuda_runtime.h>
#include <cuda_pipeline.h>
#include <cstdint>

// CTC batch cost, forward (loss only). B=128, T=1024, C=256 (blank=255),
// Lmax=64, S=129.
//
//  - one warp (one CTA) per batch element; 5 states/thread (160 >= 129, masked)
//  - alpha recurrence in PROBABILITY domain, per-thread block-floating-point
//    scales with neighbor-ratio (rho) halo rescale + frontier-safe scan renorm
//    for the first 16 chunks (unchanged from round 5, which passed @1.5e-6).
//  - THIS ROUND: emission probabilities are PRELOADED into registers one chunk
//    ahead (double-buffered pv[8][5], ~80 regs) so the 29-cycle LDS gather is
//    no longer on the recurrence critical path; m1 mask replaced by lane-0
//    rho=0 (one fewer FMA per state); rho clamped to 1e30 (dead-lane NaN
//    insurance).
//  - chunked cp.async ring: 32 stages, 24 rows prefetch, wait_prior(8) so the
//    NEXT chunk's rows are resident when we preload them.

#define T_DIM   1024
#define C_DIM   256
#define LMAX    64
#define PSTATES 5
#define NSTAGE  32
#define CHUNK   8
#define NCHUNK  (T_DIM / CHUNK)
#define SCANCH  16          // chunks using the frontier-safe scan renorm
#define EPSF    1e-7f
#define MFLOOR  1e-37f

__global__ __launch_bounds__(32, 1)
void ctc_loss_kernel(const int*   __restrict__ y_true,   // [B, LMAX]
                     const float* __restrict__ y_pred,   // [B, T, C]
                     const int*   __restrict__ in_len,   // [B, 1]
                     const int*   __restrict__ lab_len,  // [B, 1]
                     float*       __restrict__ out)      // [B, 1]
{
    __shared__ __align__(16) float stage[NSTAGE * C_DIM];
    __shared__ float fin_a [32 * PSTATES];
    __shared__ float fin_lc[32];

    const int b   = blockIdx.x;
    const int tid = threadIdx.x;
    const float* __restrict__ base = y_pred + (size_t)b * T_DIM * C_DIM;
    const int L    = lab_len[b];
    const int Tlen = in_len[b];
    const int Smax = 2 * L + 1;
    const int* __restrict__ yb = y_true + b * LMAX;

    // ---- per-state constants ----
    int   cls[PSTATES];
    float vm [PSTATES];   // 1 if state valid (s < Smax), else 0
    float evm[PSTATES];   // EPS * vm (eps folded into gather fma)
    float m2 [PSTATES];   // skip: s odd, s>=3, label != prev label
    #pragma unroll
    for (int j = 0; j < PSTATES; j++) {
        int s   = tid * PSTATES + j;
        int odd = s & 1;
        int li  = (s - 1) >> 1;
        int c   = (odd && li >= 0 && li < LMAX) ? yb[li] : (C_DIM - 1);
        bool valid = (s < Smax);
        cls[j] = c;
        vm [j] = valid ? 1.0f : 0.0f;
        evm[j] = valid ? EPSF : 0.0f;
        bool skip = odd && (s >= 3) && (li < LMAX) && (yb[li] != yb[li - 1]);
        m2 [j] = skip ? 1.0f : 0.0f;
    }

    // ---- async copy of one emission row (1 KB); always commits one group ----
    auto issue = [&](int t) {
        if (t < T_DIM) {
            const float4* src = (const float4*)(base + (size_t)t * C_DIM);
            float4*       dst = (float4*)&stage[(t & (NSTAGE - 1)) * C_DIM];
            __pipeline_memcpy_async(&dst[tid],      &src[tid],      16);
            __pipeline_memcpy_async(&dst[tid + 32], &src[tid + 32], 16);
        }
        __pipeline_commit();
    };

    float a[PSTATES];
    float logacc = 0.0f;                       // log sigma_i (per-thread scale)
    float rho    = (tid == 0) ? 0.0f : 1.0f;   // lane0 rho=0 replaces m1 mask

    // preload one chunk of emission probs (masked, eps-folded) into registers
    auto load_pv = [&](int t0, float (&pv)[CHUNK][PSTATES]) {
        #pragma unroll
        for (int i = 0; i < CHUNK; i++) {
            int t = t0 + i;
            if (t > T_DIM - 1) t = T_DIM - 1;           // harmless clamp at tail
            const float* __restrict__ row = &stage[(t & (NSTAGE - 1)) * C_DIM];
            #pragma unroll
            for (int j = 0; j < PSTATES; j++)
                pv[i][j] = fmaf(row[cls[j]], vm[j], evm[j]);
        }
    };

    // one recurrence step, emission already in registers
    auto stepr = [&](int t, const float (&p)[PSTATES]) {
        if (t < Tlen) {
            float h1 = __shfl_up_sync(0xffffffffu, a[PSTATES - 1], 1) * rho;
            float h2 = __shfl_up_sync(0xffffffffu, a[PSTATES - 2], 1) * rho;
            float na[PSTATES];
            #pragma unroll
            for (int j = 0; j < PSTATES; j++) {
                float a1 = (j == 0) ? h1 : a[j - 1];
                float a2 = (j == 0) ? h2 : ((j == 1) ? h1 : a[j - 2]);
                na[j] = fmaf(a2, m2[j], a[j] + a1) * p[j];
            }
            #pragma unroll
            for (int j = 0; j < PSTATES; j++) a[j] = na[j];
        }
    };

    auto apply_scale = [&](float v) {
        float mprev = __shfl_up_sync(0xffffffffu, v, 1);   // lane0: own v
        float rinv  = __fdividef(1.0f, v);
        logacc += __logf(v);
        rho = fminf(rho * (mprev * rinv), 1e30f);          // lane0 stays 0
        #pragma unroll
        for (int j = 0; j < PSTATES; j++) a[j] *= rinv;
    };

    // frontier-safe renorm: inactive threads adopt nearest active-below's max
    auto renorm_scan = [&]() {
        float lm = fmaxf(fmaxf(fmaxf(a[0], a[1]), fmaxf(a[2], a[3])), a[4]);
        float v  = lm;
        #pragma unroll
        for (int d = 1; d < 32; d <<= 1) {
            float up = __shfl_up_sync(0xffffffffu, v, d);
            v = (v > 0.0f) ? v : up;
        }
        v = fmaxf(v, MFLOOR);
        apply_scale(v);
    };

    // post-frontier renorm: every valid reachable thread is active forever
    auto renorm_fast = [&]() {
        float lm = fmaxf(fmaxf(fmaxf(a[0], a[1]), fmaxf(a[2], a[3])), a[4]);
        apply_scale(fmaxf(lm, MFLOOR));
    };

    float pvA[CHUNK][PSTATES];
    float pvB[CHUNK][PSTATES];

    // ---- prologue: 24 rows in flight; rows 0..7 resident; preload chunk 0 ----
    for (int k = 0; k < 3 * CHUNK; k++) issue(k);
    __pipeline_wait_prior(2 * CHUNK);      // rows 0..7 complete
    __syncwarp();
    load_pv(0, pvA);

    // ---- chunk 0: init at t=0, steps 1..7; preload chunk 1 ----
    __pipeline_wait_prior(CHUNK);          // rows 8..15 complete
    __syncwarp();
    load_pv(CHUNK, pvB);
    #pragma unroll
    for (int j = 0; j < PSTATES; j++) {
        int s = tid * PSTATES + j;
        a[j]  = (s < 2) ? pvA[0][j] : 0.0f;
    }
    #pragma unroll
    for (int i = 1; i < CHUNK; i++) stepr(i, pvA[i]);
    renorm_scan();
    #pragma unroll
    for (int k = 0; k < CHUNK; k++) issue(3 * CHUNK + k);

    // ---- chunk 1 ----
    __pipeline_wait_prior(CHUNK);
    __syncwarp();
    load_pv(2 * CHUNK, pvA);
    #pragma unroll
    for (int i = 0; i < CHUNK; i++) stepr(CHUNK + i, pvB[i]);
    renorm_scan();
    #pragma unroll
    for (int k = 0; k < CHUNK; k++) issue(4 * CHUNK + k);

    // ---- chunks 2..15 (frontier may exist): pairs, ping-pong pv ----
    for (int c = 2; c < SCANCH; c += 2) {
        int t0 = c * CHUNK;
        __pipeline_wait_prior(CHUNK);
        __syncwarp();
        load_pv(t0 + CHUNK, pvB);
        #pragma unroll
        for (int i = 0; i < CHUNK; i++) stepr(t0 + i, pvA[i]);
        renorm_scan();
        #pragma unroll
        for (int k = 0; k < CHUNK; k++) issue(t0 + 3 * CHUNK + k);

        t0 += CHUNK;
        __pipeline_wait_prior(CHUNK);
        __syncwarp();
        load_pv(t0 + CHUNK, pvA);
        #pragma unroll
        for (int i = 0; i < CHUNK; i++) stepr(t0 + i, pvB[i]);
        renorm_scan();
        #pragma unroll
        for (int k = 0; k < CHUNK; k++) issue(t0 + 3 * CHUNK + k);
    }

    // ---- chunks 16..127 (steady state): pairs, ping-pong pv ----
    for (int c = SCANCH; c < NCHUNK; c += 2) {
        int t0 = c * CHUNK;
        __pipeline_wait_prior(CHUNK);
        __syncwarp();
        load_pv(t0 + CHUNK, pvB);
        #pragma unroll
        for (int i = 0; i < CHUNK; i++) stepr(t0 + i, pvA[i]);
        renorm_fast();
        #pragma unroll
        for (int k = 0; k < CHUNK; k++) issue(t0 + 3 * CHUNK + k);

        t0 += CHUNK;
        __pipeline_wait_prior(CHUNK);
        __syncwarp();
        load_pv(t0 + CHUNK, pvA);
        #pragma unroll
        for (int i = 0; i < CHUNK; i++) stepr(t0 + i, pvB[i]);
        renorm_fast();
        #pragma unroll
        for (int k = 0; k < CHUNK; k++) issue(t0 + 3 * CHUNK + k);
    }

    // ---- finalize: ll = logaddexp over the two end states ----
    __syncwarp();
    #pragma unroll
    for (int j = 0; j < PSTATES; j++) fin_a[tid * PSTATES + j] = a[j];
    fin_lc[tid] = logacc;
    __syncwarp();
    if (tid == 0) {
        int  sa = 2 * L;
        int  sb = 2 * L - 1;                  // L >= 1 per setup
        float xa = __logf(fmaxf(fin_a[sa], MFLOOR)) + fin_lc[sa / PSTATES];
        float xb = __logf(fmaxf(fin_a[sb], MFLOOR)) + fin_lc[sb / PSTATES];
        float mxx = fmaxf(xa, xb);
        float mnn = fminf(xa, xb);
        float ll  = mxx + __logf(1.0f + __expf(mnn - mxx));
        out[b] = -ll;
    }
}

extern "C" void kernel_launch(void* const* d_in, const int* in_sizes, int n_in,
                              void* d_out, int out_size) {
    const int*   y_true  = (const int*)  d_in[0];   // [B,64] int32
    const float* y_pred  = (const float*)d_in[1];   // [B,1024,256] fp32
    const int*   in_len  = (const int*)  d_in[2];   // [B,1] int32
    const int*   lab_len = (const int*)  d_in[3];   // [B,1] int32
    float*       out     = (float*)      d_out;     // [B,1] fp32

    const int B = out_size;                          // 128
    ctc_loss_kernel<<<B, 32>>>(y_true, y_pred, in_len, lab_len, out);
}